// round 5
// baseline (speedup 1.0000x reference)
#include <cuda_runtime.h>
#include <cuda_bf16.h>

// ApproxNDCGLoss — single persistent kernel, one wave, manual grid barriers.
//
//  rank_j = 1 + sum_i sigmoid(s_j - s_i)
//         ~ 1 + sum_g [a0_g + a1_g*t + a2_g*t^2],  t = tanh((s_j - c_g)/2),
//    a0 = 0.5H - 0.25S1, a1 = 0.5H, a2 = 0.25S1  (per-bin 1st-order Taylor;
//    sum_g a0 is j-independent and folded out of the inner loop).
//  dcg  = sum_j y_j / log2(rank_j + 1)
//  idcg: exact counting-rank over an 8192-bin histogram of y in [0,1);
//    in-bin ties use bin-mean y across consecutive exact ranks (err ~1e-7).
//  loss = (sum(y) < 1) ? 0 : 1 - dcg/(idcg + 1e-8)
//
//  Replay contract: histograms are __device__ globals, zero at load; the
//  kernel re-zeroes them at the end of each run. Grid barrier uses a
//  monotonic release counter; each launch reads its base at entry (all
//  blocks read it before any block can bump it), so graph replays compose.

#define NBLK  148
#define TPB   256
#define G     512
#define YB    8192
#define YPT   (YB / TPB)          // 32 y-bins per thread (block 0)

#define S_LO  (-6.0f)
#define S_HI  ( 6.0f)

__device__ float    g_SH[2 * G];     // interleaved {H, S1} per s-bin
__device__ float    g_YC[YB];        // y-bin counts (exact integers)
__device__ float    g_YS[YB];        // y-bin value sums
__device__ float    g_dcgP[NBLK];    // per-block DCG partials
__device__ unsigned g_ctr;           // barrier arrival counter
__device__ unsigned g_release;       // barrier release generation (monotonic)

__device__ __forceinline__ float tanh_approx(float x) {
    float r;
    asm("tanh.approx.f32 %0, %1;" : "=f"(r) : "f"(x));
    return r;
}

// Generation-based single-wave grid barrier. 'target' = base + phase index.
__device__ __forceinline__ void gridbar(unsigned target) {
    __threadfence();                      // make this block's writes visible
    __syncthreads();
    if (threadIdx.x == 0) {
        const unsigned old = atomicAdd(&g_ctr, 1u);
        if (old == NBLK - 1) {
            atomicExch(&g_ctr, 0u);       // reset before release (fenced below)
            __threadfence();
            atomicExch(&g_release, target);
        } else {
            while ((int)(atomicAdd(&g_release, 0u) - target) < 0) { }
        }
    }
    __syncthreads();
}

// ---------------------------------------------------------------------------
__global__ void __launch_bounds__(TPB)
k_fused(const float* __restrict__ s, const float* __restrict__ y,
        float* __restrict__ out, int n)
{
    const int b = blockIdx.x;
    const int t = threadIdx.x;

    __shared__ unsigned s_base;
    __shared__ float2   sh[G];
    __shared__ float    r1[TPB], r2[TPB], r3[TPB];

    if (t == 0) s_base = atomicAdd(&g_release, 0u);   // pre-barrier snapshot
    __syncthreads();
    const unsigned base = s_base;

    // ---- Phase 1: histograms -------------------------------------------
    const float h     = (S_HI - S_LO) / (float)G;
    const float inv_h = (float)G / (S_HI - S_LO);

    for (int j = b * TPB + t; j < n; j += NBLK * TPB) {
        const float sv = s[j];
        int g = (int)((sv - S_LO) * inv_h);
        g = max(0, min(G - 1, g));
        const float c = S_LO + ((float)g + 0.5f) * h;
        atomicAdd(&g_SH[2 * g],     1.0f);
        atomicAdd(&g_SH[2 * g + 1], sv - c);

        const float yv = y[j];
        int q = (int)(yv * (float)YB);
        q = max(0, min(YB - 1, q));
        atomicAdd(&g_YC[q], 1.0f);
        atomicAdd(&g_YS[q], yv);
    }

    gridbar(base + 1);

    // ---- Phase 2: stage coefficients, convolve, per-block DCG ----------
    float a0loc = 0.0f;
    for (int g = t; g < G; g += TPB) {
        const float Hc = __ldcg(&g_SH[2 * g]);
        const float S1 = __ldcg(&g_SH[2 * g + 1]);
        const float a1 = 0.5f  * Hc;
        const float a2 = 0.25f * S1;
        sh[g] = make_float2(a1, a2);
        a0loc += a1 - a2;
    }
    r1[t] = a0loc;
    __syncthreads();
    #pragma unroll
    for (int off = TPB / 2; off > 0; off >>= 1) {
        if (t < off) r1[t] += r1[t + off];
        __syncthreads();
    }
    const float a0tot = r1[0];
    __syncthreads();

    const float hh = 0.5f * h;
    const float c0 = 0.5f * (S_LO + 0.5f * h);

    float dcgloc = 0.0f;
    const int per = (n + NBLK - 1) / NBLK;            // j per block
    for (int jj = t; jj < per; jj += TPB) {
        const int j = b * per + jj;
        const float sv = (j < n) ? s[j] : 0.0f;
        const float x0 = 0.5f * sv - c0;

        float acc = 0.0f;
        float tf  = 0.0f;
        #pragma unroll 8
        for (int g = 0; g < G; g++) {
            const float x  = fmaf(tf, -hh, x0);
            tf += 1.0f;
            const float th = tanh_approx(x);
            const float2 a = sh[g];
            acc = fmaf(th, fmaf(th, a.y, a.x), acc);
        }
        if (j < n) {
            const float rank = 1.0f + a0tot + acc;
            dcgloc += __fdividef(y[j], __log2f(rank + 1.0f));
        }
    }

    r1[t] = dcgloc;
    __syncthreads();
    #pragma unroll
    for (int off = TPB / 2; off > 0; off >>= 1) {
        if (t < off) r1[t] += r1[t + off];
        __syncthreads();
    }
    if (t == 0) g_dcgP[b] = r1[0];

    gridbar(base + 2);

    // ---- Phase 3: block 0 final; block 1 resets the s-histogram --------
    if (b == 1) {
        for (int i = t; i < 2 * G; i += TPB) g_SH[i] = 0.0f;
        return;
    }
    if (b != 0) return;

    // Per-thread y-bin totals (bins [t*YPT, (t+1)*YPT)).
    float Tt = 0.0f, ysum = 0.0f;
    #pragma unroll
    for (int bb = 0; bb < YPT; bb++) {
        Tt   += __ldcg(&g_YC[t * YPT + bb]);
        ysum += __ldcg(&g_YS[t * YPT + bb]);
    }

    // Inclusive suffix scan over the 256 per-thread totals.
    r1[t] = Tt;
    __syncthreads();
    #pragma unroll
    for (int off = 1; off < TPB; off <<= 1) {
        const float v = (t + off < TPB) ? r1[t + off] : 0.0f;
        __syncthreads();
        r1[t] += v;
        __syncthreads();
    }
    float above = r1[t] - Tt;     // elements strictly in higher-y threads

    // Walk own bins high -> low with exact consecutive ranks.
    float idg = 0.0f;
    #pragma unroll 4
    for (int bb = YPT - 1; bb >= 0; bb--) {
        const float cf = __ldcg(&g_YC[t * YPT + bb]);
        const int   c  = (int)cf;
        if (c > 0) {
            const float ybar = __fdividef(__ldcg(&g_YS[t * YPT + bb]), cf);
            for (int k = 1; k <= c; k++) {
                const float rank = above + (float)k;
                idg += __fdividef(ybar, __log2f(rank + 1.0f));
            }
            above += cf;
        }
    }

    // Combined reductions: idcg, sum(y), dcg-partials.
    const float d = (t < NBLK) ? __ldcg(&g_dcgP[t]) : 0.0f;
    __syncthreads();
    r1[t] = idg; r2[t] = ysum; r3[t] = d;
    __syncthreads();
    #pragma unroll
    for (int off = TPB / 2; off > 0; off >>= 1) {
        if (t < off) {
            r1[t] += r1[t + off];
            r2[t] += r2[t + off];
            r3[t] += r3[t + off];
        }
        __syncthreads();
    }
    if (t == 0) {
        const float ndcg = r3[0] / (r1[0] + 1e-8f);
        const float loss = 1.0f - ndcg;
        out[0] = (r2[0] < 1.0f) ? 0.0f : loss;
    }

    // Reset y-histograms for the next replay.
    #pragma unroll
    for (int bb = 0; bb < YPT; bb++) {
        g_YC[t * YPT + bb] = 0.0f;
        g_YS[t * YPT + bb] = 0.0f;
    }
}

// ---------------------------------------------------------------------------
extern "C" void kernel_launch(void* const* d_in, const int* in_sizes, int n_in,
                              void* d_out, int out_size)
{
    const float* s = (const float*)d_in[0];   // logits
    const float* y = (const float*)d_in[1];   // targets
    float* out = (float*)d_out;
    const int n = in_sizes[0];

    k_fused<<<NBLK, TPB>>>(s, y, out, n);
}

// round 6
// speedup vs baseline: 1.5613x; 1.5613x over previous
#include <cuda_runtime.h>
#include <cuda_bf16.h>

// ApproxNDCGLoss — 2 kernels, last-block-ticket continuations (no spin barriers).
//
//  rank_j = 1 + sum_i sigmoid(s_j - s_i)
//         ~ 1 + sum_g [a0_g + a1_g*t + a2_g*t^2],  t = tanh((s_j - c_g)/2)
//    (per-bin 1st-order Taylor over a G=512 histogram of s; validated 5.9e-7)
//  idcg: exact counting-rank over an 8192-bin y-histogram; in-bin ties use
//    bin-mean y across consecutive exact ranks. Per-bin work distributed
//    one-bin-per-thread over 64 blocks (this was the 45us single-SM tail).
//  loss = (sum(y) < 1) ? 0 : 1 - dcg/(idcg + 1e-8)
//
//  Replay contract: histograms and tickets are __device__ globals (zero at
//  load); the last block of K2 re-zeroes them each run. g_above/g_dcgP/... are
//  fully overwritten each run.

#define TPB1   256
#define TPB2   128
#define G      512
#define YB     8192
#define NIDCG  64               // 64 blocks * 128 thr = 8192 = one thread/bin
#define MAXCB  512

#define S_LO  (-6.0f)
#define S_HI  ( 6.0f)

__device__ float    g_SH[2 * G];    // interleaved {H, S1} per s-bin (atomics)
__device__ float    g_YC[YB];       // y-bin counts
__device__ float    g_YS[YB];       // y-bin value sums
__device__ float    g_above[YB];    // per-bin count of elements in higher bins
__device__ float    g_dcgP[MAXCB];
__device__ float    g_idcgP[NIDCG];
__device__ float    g_ysumP[NIDCG];
__device__ unsigned g_tick1;
__device__ unsigned g_tick2;

__device__ __forceinline__ float tanh_approx(float x) {
    float r;
    asm("tanh.approx.f32 %0, %1;" : "=f"(r) : "f"(x));
    return r;
}

// ---------------------------------------------------------------------------
// K1: histograms; last-finishing block computes the y suffix scan.
// ---------------------------------------------------------------------------
__global__ void __launch_bounds__(TPB1)
k_hist_scan(const float* __restrict__ s, const float* __restrict__ y,
            int n, int nblocks)
{
    const int t = threadIdx.x;
    const int j = blockIdx.x * TPB1 + t;

    const float h     = (S_HI - S_LO) / (float)G;
    const float inv_h = (float)G / (S_HI - S_LO);

    if (j < n) {
        const float sv = s[j];
        int g = (int)((sv - S_LO) * inv_h);
        g = max(0, min(G - 1, g));
        const float c = S_LO + ((float)g + 0.5f) * h;
        atomicAdd(&g_SH[2 * g],     1.0f);
        atomicAdd(&g_SH[2 * g + 1], sv - c);

        const float yv = y[j];
        int q = (int)(yv * (float)YB);
        q = max(0, min(YB - 1, q));
        atomicAdd(&g_YC[q], 1.0f);
        atomicAdd(&g_YS[q], yv);
    }

    // Last-block election.
    __threadfence();
    __shared__ int s_last;
    __syncthreads();
    if (t == 0) s_last = (atomicAdd(&g_tick1, 1u) == (unsigned)(nblocks - 1));
    __syncthreads();
    if (!s_last) return;

    // ---- y suffix scan: above[q] = # elements with higher y-bin ----------
    __shared__ float su[TPB1];
    const int B0 = t * (YB / TPB1);              // 32 bins per thread
    float Tt = 0.0f;
    #pragma unroll 8
    for (int b = 0; b < YB / TPB1; b++) Tt += __ldcg(&g_YC[B0 + b]);

    su[t] = Tt;
    __syncthreads();
    #pragma unroll
    for (int off = 1; off < TPB1; off <<= 1) {   // inclusive suffix scan
        const float v = (t + off < TPB1) ? su[t + off] : 0.0f;
        __syncthreads();
        su[t] += v;
        __syncthreads();
    }
    float run = su[t] - Tt;                      // strictly-higher threads
    for (int b = YB / TPB1 - 1; b >= 0; b--) {   // walk own bins high -> low
        const int q = B0 + b;
        g_above[q] = run;
        run += __ldcg(&g_YC[q]);
    }

    if (t == 0) g_tick1 = 0u;                    // reset for next replay
}

// ---------------------------------------------------------------------------
// K2: conv+DCG blocks, IDCG blocks, last-finishing block finalizes.
// ---------------------------------------------------------------------------
__global__ void __launch_bounds__(TPB2)
k_main(const float* __restrict__ s, const float* __restrict__ y,
       float* __restrict__ out, int n, int ncb, int totblocks)
{
    const int b = blockIdx.x;
    const int t = threadIdx.x;

    __shared__ float2 sh[G];
    __shared__ float  r1[TPB2], r2[TPB2];

    if (b < ncb) {
        // ---- conv + DCG ------------------------------------------------
        float a0loc = 0.0f;
        for (int g = t; g < G; g += TPB2) {
            const float Hc = __ldcg(&g_SH[2 * g]);
            const float S1 = __ldcg(&g_SH[2 * g + 1]);
            const float a1 = 0.5f  * Hc;
            const float a2 = 0.25f * S1;
            sh[g] = make_float2(a1, a2);
            a0loc += a1 - a2;
        }
        r1[t] = a0loc;
        __syncthreads();
        #pragma unroll
        for (int off = TPB2 / 2; off > 0; off >>= 1) {
            if (t < off) r1[t] += r1[t + off];
            __syncthreads();
        }
        const float a0tot = r1[0];
        __syncthreads();

        const float h  = (S_HI - S_LO) / (float)G;
        const float hh = 0.5f * h;
        const float c0 = 0.5f * (S_LO + 0.5f * h);

        const int   j  = b * TPB2 + t;
        const float sv = (j < n) ? s[j] : 0.0f;
        const float x0 = 0.5f * sv - c0;

        float acc = 0.0f;
        float tf  = 0.0f;
        #pragma unroll 8
        for (int g = 0; g < G; g++) {
            const float x  = fmaf(tf, -hh, x0);
            tf += 1.0f;
            const float th = tanh_approx(x);
            const float2 a = sh[g];
            acc = fmaf(th, fmaf(th, a.y, a.x), acc);
        }

        float dcg = 0.0f;
        if (j < n) {
            const float rank = 1.0f + a0tot + acc;
            dcg = __fdividef(y[j], __log2f(rank + 1.0f));
        }
        r1[t] = dcg;
        __syncthreads();
        #pragma unroll
        for (int off = TPB2 / 2; off > 0; off >>= 1) {
            if (t < off) r1[t] += r1[t + off];
            __syncthreads();
        }
        if (t == 0) g_dcgP[b] = r1[0];
    } else {
        // ---- IDCG: one y-bin per thread --------------------------------
        const int q = (b - ncb) * TPB2 + t;      // q in [0, YB)
        const float cf    = __ldcg(&g_YC[q]);
        const float ysum  = __ldcg(&g_YS[q]);
        const float above = __ldcg(&g_above[q]);

        float idg = 0.0f;
        const int c = (int)cf;
        if (c > 0) {
            const float ybar = __fdividef(ysum, cf);
            for (int k = 1; k <= c; k++) {
                const float rank = above + (float)k;
                idg += __fdividef(ybar, __log2f(rank + 1.0f));
            }
        }
        r1[t] = idg; r2[t] = ysum;
        __syncthreads();
        #pragma unroll
        for (int off = TPB2 / 2; off > 0; off >>= 1) {
            if (t < off) { r1[t] += r1[t + off]; r2[t] += r2[t + off]; }
            __syncthreads();
        }
        if (t == 0) {
            g_idcgP[b - ncb] = r1[0];
            g_ysumP[b - ncb] = r2[0];
        }
    }

    // ---- last-block finalize ------------------------------------------
    __threadfence();
    __shared__ int s_last;
    __syncthreads();
    if (t == 0) s_last = (atomicAdd(&g_tick2, 1u) == (unsigned)(totblocks - 1));
    __syncthreads();
    if (!s_last) return;

    float d = 0.0f, i = 0.0f, sY = 0.0f;
    for (int k = t; k < ncb; k += TPB2) d += __ldcg(&g_dcgP[k]);
    if (t < NIDCG) { i = __ldcg(&g_idcgP[t]); sY = __ldcg(&g_ysumP[t]); }
    __syncthreads();
    r1[t] = d; r2[t] = i;
    __shared__ float r3[TPB2];
    r3[t] = sY;
    __syncthreads();
    #pragma unroll
    for (int off = TPB2 / 2; off > 0; off >>= 1) {
        if (t < off) {
            r1[t] += r1[t + off];
            r2[t] += r2[t + off];
            r3[t] += r3[t + off];
        }
        __syncthreads();
    }
    if (t == 0) {
        const float ndcg = r1[0] / (r2[0] + 1e-8f);
        const float loss = 1.0f - ndcg;
        out[0] = (r3[0] < 1.0f) ? 0.0f : loss;
        g_tick2 = 0u;
    }

    // Reset histograms for the next graph replay.
    for (int k = t; k < 2 * G; k += TPB2) g_SH[k] = 0.0f;
    for (int k = t; k < YB; k += TPB2) { g_YC[k] = 0.0f; g_YS[k] = 0.0f; }
}

// ---------------------------------------------------------------------------
extern "C" void kernel_launch(void* const* d_in, const int* in_sizes, int n_in,
                              void* d_out, int out_size)
{
    const float* s = (const float*)d_in[0];   // logits
    const float* y = (const float*)d_in[1];   // targets
    float* out = (float*)d_out;
    const int n = in_sizes[0];

    const int hblocks = (n + TPB1 - 1) / TPB1;
    const int ncb     = (n + TPB2 - 1) / TPB2;      // conv blocks
    const int tot     = ncb + NIDCG;

    k_hist_scan<<<hblocks, TPB1>>>(s, y, n, hblocks);
    k_main<<<tot, TPB2>>>(s, y, out, n, ncb, tot);
}